// round 17
// baseline (speedup 1.0000x reference)
#include <cuda_runtime.h>
#include <cstdint>

// Problem constants
#define BB 2048
#define SS 512
#define DD 128
#define HH 64
#define H4 16
#define OO 8

// Scratch (device globals — no runtime allocation allowed)
__device__ float g_z1[BB * H4];
__device__ float g_mu1[HH], g_rs1[HH];
__device__ float g_mu2[H4], g_rs2[H4];

// ===========================================================================
// bf16 split helpers (layouts validated by R12/R14/R16)
// ===========================================================================
__device__ __forceinline__ void split_pair(float a, float b, uint32_t& h, uint32_t& l) {
    asm("cvt.rn.bf16x2.f32 %0, %1, %2;" : "=r"(h) : "f"(b), "f"(a));
    float ra = a - __uint_as_float(h << 16);
    float rb = b - __uint_as_float(h & 0xffff0000u);
    asm("cvt.rn.bf16x2.f32 %0, %1, %2;" : "=r"(l) : "f"(rb), "f"(ra));
}

__device__ __forceinline__ void mma_bf16(float c[4], const uint32_t a[4],
                                         uint32_t b0, uint32_t b1) {
    asm volatile(
        "mma.sync.aligned.m16n8k16.row.col.f32.bf16.bf16.f32 "
        "{%0,%1,%2,%3}, {%4,%5,%6,%7}, {%8,%9}, {%0,%1,%2,%3};"
        : "+f"(c[0]), "+f"(c[1]), "+f"(c[2]), "+f"(c[3])
        : "r"(a[0]), "r"(a[1]), "r"(a[2]), "r"(a[3]), "r"(b0), "r"(b1));
}

// ===========================================================================
// Fused RNN: h(t) = relu(x(t)@Wih^T + bias + h(t-1)@Whh^T).
//
// R17 (hybrid): kernel is tensor-ISSUE bound at HMMA rt~16 (72 MMA = 1152
// cyc/step in R16). Offload h's k in [32,64) to the idle fp32 FMA pipe:
//  - tensor: xp 48 MMAs + h kc0,kc1 = 60 MMAs (~960 cyc)
//  - scalar: lane owns 1 col x 8 rows x 32 k = 256 FMA (exact fp32), partial
//    sums exchanged via smem, merged into C next step.
// At relu, lanes store h VALUES (scalar path input) + h-frags for kc0,kc1
// only (warps 0,1). Barrier structure identical to R16; every new smem
// read/write pair straddles an existing barrier (checked per-pair).
// ===========================================================================
#define F_THREADS 128
#define F_GRID (BB / 16)   // 128

__global__ void __launch_bounds__(F_THREADS, 1)
rnn_fused_kernel(const float* __restrict__ x, const float* __restrict__ h0,
                 const float* __restrict__ Wih, const float* __restrict__ Whh,
                 const float* __restrict__ bih, const float* __restrict__ bhh,
                 float* __restrict__ hT_out) {
    __shared__ float s_xraw[3][16 * DD];      // raw x tiles (3 x 8KB)
    __shared__ uint4 s_xfh[2][8 * 32];        // x A-frags hi (2 x 4KB)
    __shared__ uint4 s_xfl[2][8 * 32];        // x A-frags lo (2 x 4KB)
    __shared__ uint4 s_hfh[2][2 * 32];        // h A-frags hi, kc0-1 only
    __shared__ uint4 s_hfl[2][2 * 32];        // h A-frags lo, kc0-1 only
    __shared__ float s_hval[16][68];          // h values (scalar-path input)
    __shared__ float s_part[16][68];          // scalar partial sums

    const int tid  = threadIdx.x;
    const int w    = tid >> 5;
    const int lane = tid & 31;
    const int g    = lane >> 2;
    const int qb   = (lane & 3) * 2;
    const int gb0  = blockIdx.x * 16;
    const int scol = tid >> 1;                // scalar path: col 0..63
    const int srh  = tid & 1;                 // scalar path: row half

    // ---- B fragments in registers ----
    uint32_t wih_h[2][8][2], wih_l[2][8][2];
    uint32_t whh_h[2][2][2], whh_l[2][2][2];  // kc0,kc1 only
    float bias0[2], bias1[2];
#pragma unroll
    for (int nt = 0; nt < 2; nt++) {
        const int n = 2 * w + nt;
        const float* wr = Wih + (n * 8 + g) * DD;
#pragma unroll
        for (int kc = 0; kc < 8; kc++) {
            const float* p = wr + kc * 16 + qb;
            split_pair(p[0], p[1], wih_h[nt][kc][0], wih_l[nt][kc][0]);
            split_pair(p[8], p[9], wih_h[nt][kc][1], wih_l[nt][kc][1]);
        }
        const float* hr = Whh + (n * 8 + g) * HH;
#pragma unroll
        for (int kc = 0; kc < 2; kc++) {
            const float* p = hr + kc * 16 + qb;
            split_pair(p[0], p[1], whh_h[nt][kc][0], whh_l[nt][kc][0]);
            split_pair(p[8], p[9], whh_h[nt][kc][1], whh_l[nt][kc][1]);
        }
        bias0[nt] = bih[n * 8 + qb]     + bhh[n * 8 + qb];
        bias1[nt] = bih[n * 8 + qb + 1] + bhh[n * 8 + qb + 1];
    }

    // ---- scalar-path W registers: Whh[scol][32..63] ----
    float wsc[32];
#pragma unroll
    for (int j = 0; j < 8; j++) {
        float4 v = *(const float4*)(Whh + scol * HH + 32 + 4 * j);
        wsc[4*j] = v.x; wsc[4*j+1] = v.y; wsc[4*j+2] = v.z; wsc[4*j+3] = v.w;
    }

    // ---- h(-1) = h0: values for all, frags (kc=w) for warps 0,1 ----
    {
        const float* hb = h0 + (size_t)gb0 * HH;
        for (int idx = tid; idx < 16 * HH; idx += F_THREADS)
            s_hval[idx >> 6][idx & 63] = hb[idx];
        if (w < 2) {
            uint4 hh, hl;
            split_pair(hb[g * HH + 16 * w + qb],        hb[g * HH + 16 * w + qb + 1],       hh.x, hl.x);
            split_pair(hb[(g + 8) * HH + 16 * w + qb],  hb[(g + 8) * HH + 16 * w + qb + 1], hh.y, hl.y);
            split_pair(hb[g * HH + 16 * w + 8 + qb],       hb[g * HH + 16 * w + 8 + qb + 1],       hh.z, hl.z);
            split_pair(hb[(g + 8) * HH + 16 * w + 8 + qb], hb[(g + 8) * HH + 16 * w + 8 + qb + 1], hh.w, hl.w);
            s_hfh[0][w * 32 + lane] = hh;
            s_hfl[0][w * 32 + lane] = hl;
        }
    }

    // ---- cp.async stage of x(t) tile into raw buf ----
    auto stage_x = [&](int buf, int t) {
        uint32_t dst0;
        asm("{ .reg .u64 a; cvta.to.shared.u64 a, %1; cvt.u32.u64 %0, a; }"
            : "=r"(dst0) : "l"(&s_xraw[buf][0]));
#pragma unroll
        for (int i = 0; i < 4; i++) {
            int u = tid * 4 + i;
            int r = u >> 5, c16 = u & 31;
            const float* src = x + ((size_t)(gb0 + r) * SS + t) * DD + c16 * 4;
            asm volatile("cp.async.cg.shared.global [%0], [%1], 16;"
                         :: "r"(dst0 + u * 16), "l"(src));
        }
        asm volatile("cp.async.commit_group;" ::: "memory");
    };

    auto convert_x = [&](int rawbuf, int fbuf) {
#pragma unroll
        for (int s = 0; s < 2; s++) {
            int slot = tid + s * 128;
            int kc = slot >> 5, l = slot & 31;
            int g2 = l >> 2, q2 = (l & 3) * 2;
            const float* xr = &s_xraw[rawbuf][0];
            float2 p0 = *(const float2*)(xr + g2 * DD + kc * 16 + q2);
            float2 p1 = *(const float2*)(xr + (g2 + 8) * DD + kc * 16 + q2);
            float2 p2 = *(const float2*)(xr + g2 * DD + kc * 16 + q2 + 8);
            float2 p3 = *(const float2*)(xr + (g2 + 8) * DD + kc * 16 + q2 + 8);
            uint4 fh, fl;
            split_pair(p0.x, p0.y, fh.x, fl.x);
            split_pair(p1.x, p1.y, fh.y, fl.y);
            split_pair(p2.x, p2.y, fh.z, fl.z);
            split_pair(p3.x, p3.y, fh.w, fl.w);
            s_xfh[fbuf][slot] = fh;
            s_xfl[fbuf][slot] = fl;
        }
    };

    // scalar partial: part[row][scol] = sum_{k=32..63} h[row][k] * Whh[scol][k]
    auto scalar_partial = [&]() {
        float acc[8];
#pragma unroll
        for (int r = 0; r < 8; r++) acc[r] = 0.0f;
#pragma unroll
        for (int j = 0; j < 8; j++) {
#pragma unroll
            for (int r = 0; r < 8; r++) {
                const float4 hv = *(const float4*)&s_hval[srh * 8 + r][32 + 4 * j];
                acc[r] = fmaf(hv.x, wsc[4*j],
                         fmaf(hv.y, wsc[4*j+1],
                         fmaf(hv.z, wsc[4*j+2],
                         fmaf(hv.w, wsc[4*j+3], acc[r]))));
            }
        }
#pragma unroll
        for (int r = 0; r < 8; r++) s_part[srh * 8 + r][scol] = acc[r];
    };

    // ---- prologue ----
    stage_x(0, 0);
    stage_x(1, 1);
    stage_x(2, 2);
    asm volatile("cp.async.wait_group 0;" ::: "memory");
    __syncthreads();               // h0 vals/frags + x(0) visible
    convert_x(0, 0);
    scalar_partial();              // partial(-1) from h0
    __syncthreads();

    float C[2][3][4];
    auto xp_mma = [&](int fbuf) {
#pragma unroll
        for (int nt = 0; nt < 2; nt++) {
            C[nt][0][0] = bias0[nt]; C[nt][0][1] = bias1[nt];
            C[nt][0][2] = bias0[nt]; C[nt][0][3] = bias1[nt];
#pragma unroll
            for (int i = 0; i < 4; i++) { C[nt][1][i] = 0.0f; C[nt][2][i] = 0.0f; }
        }
#pragma unroll
        for (int kc = 0; kc < 8; kc++) {
            uint4 ahv = s_xfh[fbuf][kc * 32 + lane];
            uint4 alv = s_xfl[fbuf][kc * 32 + lane];
            uint32_t ah[4] = {ahv.x, ahv.y, ahv.z, ahv.w};
            uint32_t al[4] = {alv.x, alv.y, alv.z, alv.w};
#pragma unroll
            for (int nt = 0; nt < 2; nt++) {
                mma_bf16(C[nt][0], ah, wih_h[nt][kc][0], wih_h[nt][kc][1]);
                mma_bf16(C[nt][1], al, wih_h[nt][kc][0], wih_h[nt][kc][1]);
                mma_bf16(C[nt][2], ah, wih_l[nt][kc][0], wih_l[nt][kc][1]);
            }
        }
    };
    xp_mma(0);   // C = bias + xp(0)

    int pb = 0, xb = 1;
    for (int i = 0; i < SS; i++) {
        // ---- tensor h-MMA: k in [0,32) ----
#pragma unroll
        for (int kc = 0; kc < 2; kc++) {
            uint4 ahv = s_hfh[pb][kc * 32 + lane];
            uint4 alv = s_hfl[pb][kc * 32 + lane];
            uint32_t ah[4] = {ahv.x, ahv.y, ahv.z, ahv.w};
            uint32_t al[4] = {alv.x, alv.y, alv.z, alv.w};
#pragma unroll
            for (int nt = 0; nt < 2; nt++) {
                mma_bf16(C[nt][0], ah, whh_h[nt][kc][0], whh_h[nt][kc][1]);
                mma_bf16(C[nt][1], al, whh_h[nt][kc][0], whh_h[nt][kc][1]);
                mma_bf16(C[nt][2], ah, whh_l[nt][kc][0], whh_l[nt][kc][1]);
            }
        }
        // ---- merge scalar partial (k in [32,64)) into chain 0 ----
#pragma unroll
        for (int nt = 0; nt < 2; nt++) {
            const int c0 = (2 * w + nt) * 8 + qb;
            float2 pa = *(const float2*)&s_part[g][c0];
            float2 pc = *(const float2*)&s_part[g + 8][c0];
            C[nt][0][0] += pa.x; C[nt][0][1] += pa.y;
            C[nt][0][2] += pc.x; C[nt][0][3] += pc.y;
        }
        // ---- sum chains + relu ----
        float v00 = fmaxf((C[0][0][0] + C[0][1][0]) + C[0][2][0], 0.0f);
        float v01 = fmaxf((C[0][0][1] + C[0][1][1]) + C[0][2][1], 0.0f);
        float v02 = fmaxf((C[0][0][2] + C[0][1][2]) + C[0][2][2], 0.0f);
        float v03 = fmaxf((C[0][0][3] + C[0][1][3]) + C[0][2][3], 0.0f);
        float v10 = fmaxf((C[1][0][0] + C[1][1][0]) + C[1][2][0], 0.0f);
        float v11 = fmaxf((C[1][0][1] + C[1][1][1]) + C[1][2][1], 0.0f);
        float v12 = fmaxf((C[1][0][2] + C[1][1][2]) + C[1][2][2], 0.0f);
        float v13 = fmaxf((C[1][0][3] + C[1][1][3]) + C[1][2][3], 0.0f);

        if (i == SS - 1) {
            float* hb = hT_out + (size_t)gb0 * HH;
            *(float2*)(hb + g * HH + (2 * w) * 8 + qb)       = make_float2(v00, v01);
            *(float2*)(hb + (g + 8) * HH + (2 * w) * 8 + qb) = make_float2(v02, v03);
            *(float2*)(hb + g * HH + (2 * w + 1) * 8 + qb)       = make_float2(v10, v11);
            *(float2*)(hb + (g + 8) * HH + (2 * w + 1) * 8 + qb) = make_float2(v12, v13);
            break;
        }

        // ---- store h(i): values (all warps) + frags kc=w (warps 0,1) ----
        {
            const int c0 = (2 * w) * 8 + qb, c1 = (2 * w + 1) * 8 + qb;
            *(float2*)&s_hval[g][c0]     = make_float2(v00, v01);
            *(float2*)&s_hval[g + 8][c0] = make_float2(v02, v03);
            *(float2*)&s_hval[g][c1]     = make_float2(v10, v11);
            *(float2*)&s_hval[g + 8][c1] = make_float2(v12, v13);
            if (w < 2) {
                uint4 hh, hl;
                split_pair(v00, v01, hh.x, hl.x);
                split_pair(v02, v03, hh.y, hl.y);
                split_pair(v10, v11, hh.z, hl.z);
                split_pair(v12, v13, hh.w, hl.w);
                s_hfh[pb ^ 1][w * 32 + lane] = hh;
                s_hfl[pb ^ 1][w * 32 + lane] = hl;
            }
        }

        // ---- x pipeline (R16-proven): wait -> B1 -> stage/convert ----
        if (i >= SS - 2) {
            asm volatile("cp.async.wait_group 0;" ::: "memory");
        } else {
            asm volatile("cp.async.wait_group 1;" ::: "memory");
        }
        __syncthreads();   // B1: h vals/frags + other threads' cp.async visible

        if (i + 3 < SS) stage_x((i + 3) % 3, i + 3);
        convert_x((i + 1) % 3, xb);
        scalar_partial();  // partial(i) from h(i) values (visible since B1)

        __syncthreads();   // B2: x-frags + partial visible

        // ---- xp-MMA for step i+1 ----
        xp_mma(xb);

        pb ^= 1;
        xb ^= 1;
    }
}

// ===========================================================================
// head kernels (proven)
// ===========================================================================
__global__ void bn1_stats_kernel(const float* __restrict__ hT) {
    const int f = blockIdx.x, tid = threadIdx.x;
    __shared__ float red[256];
    __shared__ float s_mu;

    float s = 0.0f;
    for (int b = tid; b < BB; b += 256) s += hT[b * HH + f];
    red[tid] = s;
    __syncthreads();
    for (int w = 128; w > 0; w >>= 1) {
        if (tid < w) red[tid] += red[tid + w];
        __syncthreads();
    }
    if (tid == 0) s_mu = red[0] * (1.0f / BB);
    __syncthreads();
    const float mu = s_mu;

    float s2 = 0.0f;
    for (int b = tid; b < BB; b += 256) {
        float v = hT[b * HH + f] - mu;
        s2 += v * v;
    }
    red[tid] = s2;
    __syncthreads();
    for (int w = 128; w > 0; w >>= 1) {
        if (tid < w) red[tid] += red[tid + w];
        __syncthreads();
    }
    if (tid == 0) {
        g_mu1[f] = mu;
        g_rs1[f] = rsqrtf(red[0] * (1.0f / BB) + 1e-5f);
    }
}

__global__ void fc1_kernel(const float* __restrict__ hT,
                           const float* __restrict__ g1, const float* __restrict__ be1,
                           const float* __restrict__ fW, const float* __restrict__ fb) {
    __shared__ float sW[H4 * HH];
    __shared__ float sc[HH], sh[HH], sb[H4];
    const int tid = threadIdx.x;
    for (int i = tid; i < H4 * HH; i += 128) sW[i] = fW[i];
    if (tid < HH) {
        float s = g_rs1[tid] * g1[tid];
        sc[tid] = s;
        sh[tid] = be1[tid] - g_mu1[tid] * s;
    }
    if (tid < H4) sb[tid] = fb[tid];
    __syncthreads();

    const int b = blockIdx.x * 128 + tid;
    float acc[H4];
#pragma unroll
    for (int o = 0; o < H4; o++) acc[o] = sb[o];
#pragma unroll 8
    for (int j = 0; j < HH; j++) {
        float v = fmaf(hT[b * HH + j], sc[j], sh[j]);
#pragma unroll
        for (int o = 0; o < H4; o++) acc[o] = fmaf(v, sW[o * HH + j], acc[o]);
    }
#pragma unroll
    for (int o = 0; o < H4; o++) g_z1[b * H4 + o] = fmaxf(acc[o], 0.0f);
}

__global__ void bn2_stats_kernel() {
    __shared__ float rs[8][H4], rq[8][H4];
    const int tid = threadIdx.x, lane = tid & 31, w = tid >> 5;

    float s[H4], q[H4];
#pragma unroll
    for (int i = 0; i < H4; i++) { s[i] = 0.0f; q[i] = 0.0f; }

    for (int b = tid; b < BB; b += 256) {
        const float4* p = (const float4*)(g_z1 + b * H4);
#pragma unroll
        for (int u = 0; u < 4; u++) {
            float4 v = p[u];
            s[u*4+0] += v.x; q[u*4+0] += v.x * v.x;
            s[u*4+1] += v.y; q[u*4+1] += v.y * v.y;
            s[u*4+2] += v.z; q[u*4+2] += v.z * v.z;
            s[u*4+3] += v.w; q[u*4+3] += v.w * v.w;
        }
    }
#pragma unroll
    for (int i = 0; i < H4; i++) {
#pragma unroll
        for (int d = 16; d > 0; d >>= 1) {
            s[i] += __shfl_xor_sync(0xFFFFFFFFu, s[i], d);
            q[i] += __shfl_xor_sync(0xFFFFFFFFu, q[i], d);
        }
    }
    if (lane == 0) {
#pragma unroll
        for (int i = 0; i < H4; i++) { rs[w][i] = s[i]; rq[w][i] = q[i]; }
    }
    __syncthreads();
    if (tid < H4) {
        float S = 0.0f, Q = 0.0f;
#pragma unroll
        for (int w2 = 0; w2 < 8; w2++) { S += rs[w2][tid]; Q += rq[w2][tid]; }
        float mu = S * (1.0f / BB);
        g_mu2[tid] = mu;
        g_rs2[tid] = rsqrtf(fmaxf(Q * (1.0f / BB) - mu * mu, 0.0f) + 1e-5f);
    }
}

__global__ void fc2_kernel(const float* __restrict__ g2, const float* __restrict__ be2,
                           const float* __restrict__ fW, const float* __restrict__ fb,
                           float* __restrict__ out) {
    __shared__ float sW[OO * H4];
    __shared__ float sc[H4], sh[H4], sb[OO];
    const int tid = threadIdx.x;
    if (tid < OO * H4) sW[tid] = fW[tid];
    if (tid < H4) {
        float s = g_rs2[tid] * g2[tid];
        sc[tid] = s;
        sh[tid] = be2[tid] - g_mu2[tid] * s;
    }
    if (tid < OO) sb[tid] = fb[tid];
    __syncthreads();

    const int b = blockIdx.x * 256 + tid;
    float z[H4];
#pragma unroll
    for (int o = 0; o < H4; o++) z[o] = fmaf(g_z1[b * H4 + o], sc[o], sh[o]);
#pragma unroll
    for (int c = 0; c < OO; c++) {
        float a = sb[c];
#pragma unroll
        for (int o = 0; o < H4; o++) a = fmaf(z[o], sW[c * H4 + o], a);
        out[b * OO + c] = a;
    }
}

// ---------------------------------------------------------------------------
// Launch. d_out layout: [0, B*O) = out; [B*O, B*O+B*H) = hT.
// ---------------------------------------------------------------------------
extern "C" void kernel_launch(void* const* d_in, const int* in_sizes, int n_in,
                              void* d_out, int out_size) {
    const float* x    = (const float*)d_in[0];
    const float* h0   = (const float*)d_in[1];
    const float* Wih  = (const float*)d_in[2];
    const float* Whh  = (const float*)d_in[3];
    const float* bih  = (const float*)d_in[4];
    const float* bhh  = (const float*)d_in[5];
    const float* bn1g = (const float*)d_in[6];
    const float* bn1b = (const float*)d_in[7];
    const float* fc1W = (const float*)d_in[8];
    const float* fc1b = (const float*)d_in[9];
    const float* bn2g = (const float*)d_in[10];
    const float* bn2b = (const float*)d_in[11];
    const float* fc2W = (const float*)d_in[12];
    const float* fc2b = (const float*)d_in[13];

    float* out = (float*)d_out;
    float* hT  = out + BB * OO;

    rnn_fused_kernel<<<F_GRID, F_THREADS>>>(x, h0, Wih, Whh, bih, bhh, hT);
    bn1_stats_kernel<<<HH, 256>>>(hT);
    fc1_kernel<<<BB / 128, 128>>>(hT, bn1g, bn1b, fc1W, fc1b);
    bn2_stats_kernel<<<1, 256>>>();
    fc2_kernel<<<BB / 256, 256>>>(bn2g, bn2b, fc2W, fc2b, out);
}